// round 1
// baseline (speedup 1.0000x reference)
#include <cuda_runtime.h>
#include <math.h>

#define GRID_BLOCKS 128
#define NTHREADS    256
#define Bsz   256
#define Hh    512
#define SRCT  512
#define TGTT  96
#define INMM  64

// ---------------- persistent device scratch (no allocations allowed) ----------------
__device__ float d_H0[2][Bsz * Hh];   // encoder layer0 h ping-pong
__device__ float d_H1[2][Bsz * Hh];   // encoder layer1 h ping-pong
__device__ float d_Hd0[2][Bsz * Hh];  // decoder layer0 h ping-pong (parity 0 = enc final h0)
__device__ float d_Hd1[2][Bsz * Hh];  // decoder layer1 h ping-pong (parity 0 = enc final h1)
__device__ float d_FCA[Bsz * Hh];     // fc hidden activation
__device__ float d_XD[Bsz];           // decoder scalar input
__device__ unsigned g_cnt;            // barrier arrive counter (self-resetting)
__device__ unsigned g_gen;            // barrier generation (monotonic, wrap-safe)

struct SM { float As[64][68]; float Ws[64][68]; };

// ---------------- grid-wide barrier (all 128 blocks resident) ----------------
__device__ __forceinline__ void grid_sync()
{
    __syncthreads();
    if (threadIdx.x == 0) {
        unsigned gen = *((volatile unsigned*)&g_gen);
        __threadfence();
        if (atomicAdd(&g_cnt, 1u) == GRID_BLOCKS - 1) {
            atomicExch(&g_cnt, 0u);
            __threadfence();
            atomicAdd(&g_gen, 1u);
        } else {
            while (*((volatile unsigned*)&g_gen) == gen) { __nanosleep(64); }
        }
    }
    __syncthreads();
}

// ---------------- 64x64 block GEMM: acc[bi][gate] += A[64xK] * W[64xK]^T ----------------
// thread (bg,jj): rows bg*4+bi, cols gate*16+jj
template <class FA, class FW>
__device__ __forceinline__ void gemm64(SM& s, FA aload, FW wload, int Kpad, float acc[4][4])
{
    const int tid = threadIdx.x;
    const int bg = tid >> 4, jj = tid & 15;
    #pragma unroll 1
    for (int k0 = 0; k0 < Kpad; k0 += 64) {
        #pragma unroll
        for (int l = 0; l < 16; ++l) {
            int idx = tid + l * 256;
            int r = idx >> 6, k = idx & 63;
            s.As[r][k] = aload(r, k0 + k);
            s.Ws[r][k] = wload(r, k0 + k);
        }
        __syncthreads();
        #pragma unroll
        for (int kk = 0; kk < 64; kk += 4) {
            float4 a0 = *(const float4*)&s.As[bg * 4 + 0][kk];
            float4 a1 = *(const float4*)&s.As[bg * 4 + 1][kk];
            float4 a2 = *(const float4*)&s.As[bg * 4 + 2][kk];
            float4 a3 = *(const float4*)&s.As[bg * 4 + 3][kk];
            float4 w0 = *(const float4*)&s.Ws[ 0 + jj][kk];
            float4 w1 = *(const float4*)&s.Ws[16 + jj][kk];
            float4 w2 = *(const float4*)&s.Ws[32 + jj][kk];
            float4 w3 = *(const float4*)&s.Ws[48 + jj][kk];
            #define DOT4(ACC, A, W) ACC += A.x*W.x; ACC += A.y*W.y; ACC += A.z*W.z; ACC += A.w*W.w;
            DOT4(acc[0][0], a0, w0) DOT4(acc[0][1], a0, w1) DOT4(acc[0][2], a0, w2) DOT4(acc[0][3], a0, w3)
            DOT4(acc[1][0], a1, w0) DOT4(acc[1][1], a1, w1) DOT4(acc[1][2], a1, w2) DOT4(acc[1][3], a1, w3)
            DOT4(acc[2][0], a2, w0) DOT4(acc[2][1], a2, w1) DOT4(acc[2][2], a2, w2) DOT4(acc[2][3], a2, w3)
            DOT4(acc[3][0], a3, w0) DOT4(acc[3][1], a3, w1) DOT4(acc[3][2], a3, w2) DOT4(acc[3][3], a3, w3)
            #undef DOT4
        }
        __syncthreads();
    }
}

__device__ __forceinline__ float sigmoidf_(float x) { return 1.f / (1.f + expf(-x)); }

// ---------------- LSTM pointwise cell + h store (c stays in registers) ----------------
__device__ __forceinline__ void cell_store(const float acc[4][4], float creg[4], const float bias[4],
                                           int b0, int bg, int j,
                                           float* __restrict__ hdst, float* __restrict__ hdst2)
{
    #pragma unroll
    for (int bi = 0; bi < 4; ++bi) {
        float pi = acc[bi][0] + bias[0];
        float pf = acc[bi][1] + bias[1];
        float pg = acc[bi][2] + bias[2];
        float po = acc[bi][3] + bias[3];
        float ii = sigmoidf_(pi);
        float ff = sigmoidf_(pf);
        float gg = tanhf(pg);
        float oo = sigmoidf_(po);
        float c = ff * creg[bi] + ii * gg;
        creg[bi] = c;
        float h = oo * tanhf(c);
        int b = b0 + bg * 4 + bi;
        hdst[b * Hh + j] = h;
        if (hdst2) hdst2[b * Hh + j] = h;
    }
}

extern "C" __global__ void __launch_bounds__(NTHREADS, 1)
lstm_seq2seq(const float* __restrict__ src, const float* __restrict__ tgt,
             const float* __restrict__ eW0i, const float* __restrict__ eW0h,
             const float* __restrict__ eB0i, const float* __restrict__ eB0h,
             const float* __restrict__ dW0i, const float* __restrict__ dW0h,
             const float* __restrict__ dB0i, const float* __restrict__ dB0h,
             const float* __restrict__ eW1i, const float* __restrict__ eW1h,
             const float* __restrict__ eB1i, const float* __restrict__ eB1h,
             const float* __restrict__ dW1i, const float* __restrict__ dW1h,
             const float* __restrict__ dB1i, const float* __restrict__ dB1h,
             const float* __restrict__ fW0, const float* __restrict__ fb0,
             const float* __restrict__ fW1, const float* __restrict__ fb1,
             float* __restrict__ out)
{
    __shared__ SM s;
    const int tid = threadIdx.x;
    const int blk = blockIdx.x;
    const int jt = blk & 31;   // 32 j-tiles of 16 h-columns
    const int mt = blk >> 5;   // 4 batch tiles of 64
    const int b0 = mt * 64;
    const int bg = tid >> 4, jj = tid & 15;
    const int j = jt * 16 + jj;

    // hoisted per-thread biases (one (gate, j) set per thread)
    float biasE0[4], biasE1[4], biasD0[4], biasD1[4];
    #pragma unroll
    for (int gate = 0; gate < 4; ++gate) {
        int g = gate * Hh + j;
        biasE0[gate] = eB0i[g] + eB0h[g];
        biasE1[gate] = eB1i[g] + eB1h[g];
        biasD0[gate] = dB0i[g] + dB0h[g];
        biasD1[gate] = dB1i[g] + dB1h[g];
    }

    // ---- init: zero h ping-pongs, load decoder x0 ----
    #pragma unroll
    for (int bi = 0; bi < 4; ++bi) {
        int b = b0 + bg * 4 + bi;
        d_H0[0][b * Hh + j] = 0.f; d_H0[1][b * Hh + j] = 0.f;
        d_H1[0][b * Hh + j] = 0.f; d_H1[1][b * Hh + j] = 0.f;
    }
    if (jt == 0 && tid < 64) d_XD[b0 + tid] = tgt[(b0 + tid) * TGTT];

    float cA[4] = {0.f, 0.f, 0.f, 0.f};   // enc0 -> dec0 cell state (same block owns same (b,j))
    float cB[4] = {0.f, 0.f, 0.f, 0.f};   // enc1 -> dec1 cell state
    grid_sync();

    // ================= encoder (wavefront: L0 step t || L1 step t-1) =================
    int p0 = 0, p1 = 0;
    for (int st = 0; st <= SRCT; ++st) {
        if (st < SRCT) {                       // layer 0 at t = st
            const int t = st;
            float acc[4][4] = {};
            const float* Hrd = d_H0[p0];
            auto al = [&](int r, int k) -> float {
                int b = b0 + r;
                if (k < INMM) return __ldg(&src[(size_t)b * SRCT * INMM + t * INMM + k]);
                return __ldcg(&Hrd[b * Hh + (k - INMM)]);
            };
            auto wl = [&](int c, int k) -> float {
                int g = (c >> 4) * Hh + jt * 16 + (c & 15);
                if (k < INMM) return __ldg(&eW0i[g * INMM + k]);
                return __ldg(&eW0h[g * Hh + k - INMM]);
            };
            gemm64(s, al, wl, INMM + Hh, acc);
            cell_store(acc, cA, biasE0, b0, bg, j, d_H0[p0 ^ 1],
                       (t == SRCT - 1) ? d_Hd0[0] : (float*)nullptr);
        }
        if (st >= 1) {                         // layer 1 at t = st-1
            const int t = st - 1;
            float acc[4][4] = {};
            const float* Xrd = d_H0[p0];       // enc0 output at t (written last super-step)
            const float* Hrd = d_H1[p1];
            auto al = [&](int r, int k) -> float {
                int b = b0 + r;
                if (k < Hh) return __ldcg(&Xrd[b * Hh + k]);
                return __ldcg(&Hrd[b * Hh + (k - Hh)]);
            };
            auto wl = [&](int c, int k) -> float {
                int g = (c >> 4) * Hh + jt * 16 + (c & 15);
                if (k < Hh) return __ldg(&eW1i[g * Hh + k]);
                return __ldg(&eW1h[g * Hh + k - Hh]);
            };
            gemm64(s, al, wl, 2 * Hh, acc);
            cell_store(acc, cB, biasE1, b0, bg, j, d_H1[p1 ^ 1],
                       (t == SRCT - 1) ? d_Hd1[0] : (float*)nullptr);
        }
        grid_sync();
        p0 ^= 1; p1 ^= 1;
    }

    // ================= autoregressive decoder =================
    int pd0 = 0, pd1 = 0;
    for (int t = 0; t < TGTT; ++t) {
        // ---- stage A: decoder layer 0 (input = scalar x) ----
        {
            float acc[4][4] = {};
            const float* Hrd = d_Hd0[pd0];
            auto al = [&](int r, int k) -> float {
                int b = b0 + r;
                if (k == 0) return __ldcg(&d_XD[b]);
                if (k < 513) return __ldcg(&Hrd[b * Hh + k - 1]);
                return 0.f;
            };
            auto wl = [&](int c, int k) -> float {
                int g = (c >> 4) * Hh + jt * 16 + (c & 15);
                if (k == 0) return __ldg(&dW0i[g]);
                if (k < 513) return __ldg(&dW0h[g * Hh + k - 1]);
                return 0.f;
            };
            gemm64(s, al, wl, 576, acc);
            cell_store(acc, cA, biasD0, b0, bg, j, d_Hd0[pd0 ^ 1], (float*)nullptr);
        }
        grid_sync(); pd0 ^= 1;

        // ---- stage B: decoder layer 1 ----
        {
            float acc[4][4] = {};
            const float* Xrd = d_Hd0[pd0];     // fresh h0
            const float* Hrd = d_Hd1[pd1];
            auto al = [&](int r, int k) -> float {
                int b = b0 + r;
                if (k < Hh) return __ldcg(&Xrd[b * Hh + k]);
                return __ldcg(&Hrd[b * Hh + k - Hh]);
            };
            auto wl = [&](int c, int k) -> float {
                int g = (c >> 4) * Hh + jt * 16 + (c & 15);
                if (k < Hh) return __ldg(&dW1i[g * Hh + k]);
                return __ldg(&dW1h[g * Hh + k - Hh]);
            };
            gemm64(s, al, wl, 2 * Hh, acc);
            cell_store(acc, cB, biasD1, b0, bg, j, d_Hd1[pd1 ^ 1], (float*)nullptr);
        }
        grid_sync(); pd1 ^= 1;

        // ---- stage C: fc hidden = relu(relu(h1) @ W0^T + b0), blocks jt<8 ----
        if (jt < 8) {
            float acc[4][4] = {};
            const float* Hrd = d_Hd1[pd1];
            auto al = [&](int r, int k) -> float {
                float v = __ldcg(&Hrd[(b0 + r) * Hh + k]);
                return v > 0.f ? v : 0.f;
            };
            auto wl = [&](int c, int k) -> float {
                int gc = jt * 64 + c;
                return __ldg(&fW0[gc * Hh + k]);
            };
            gemm64(s, al, wl, Hh, acc);
            #pragma unroll
            for (int q = 0; q < 4; ++q) {
                int gc = jt * 64 + q * 16 + jj;
                float bb = __ldg(&fb0[gc]);
                #pragma unroll
                for (int bi = 0; bi < 4; ++bi) {
                    float v = acc[bi][q] + bb;
                    d_FCA[(b0 + bg * 4 + bi) * Hh + gc] = v > 0.f ? v : 0.f;
                }
            }
        }
        grid_sync();

        // ---- stage D: out = a @ W1^T + b1 (scalar), feed back as next x ----
        if (jt == 0) {
            int bb = tid >> 2, q = tid & 3;
            int b = b0 + bb;
            float sum = 0.f;
            for (int k = q * 128; k < q * 128 + 128; k += 4) {
                float4 av = __ldcg((const float4*)&d_FCA[b * Hh + k]);
                float4 wv = *(const float4*)&fW1[k];
                sum += av.x * wv.x + av.y * wv.y + av.z * wv.z + av.w * wv.w;
            }
            sum += __shfl_xor_sync(0xffffffffu, sum, 1);
            sum += __shfl_xor_sync(0xffffffffu, sum, 2);
            if (q == 0) {
                float o = sum + __ldg(&fb1[0]);
                out[b * TGTT + t] = o;
                d_XD[b] = o;
            }
        }
        grid_sync();
    }
}

extern "C" void kernel_launch(void* const* d_in, const int* in_sizes, int n_in,
                              void* d_out, int out_size)
{
    const float* src  = (const float*)d_in[0];
    const float* tgt  = (const float*)d_in[1];
    const float* eW0i = (const float*)d_in[2];
    const float* eW0h = (const float*)d_in[3];
    const float* eB0i = (const float*)d_in[4];
    const float* eB0h = (const float*)d_in[5];
    const float* dW0i = (const float*)d_in[6];
    const float* dW0h = (const float*)d_in[7];
    const float* dB0i = (const float*)d_in[8];
    const float* dB0h = (const float*)d_in[9];
    const float* eW1i = (const float*)d_in[10];
    const float* eW1h = (const float*)d_in[11];
    const float* eB1i = (const float*)d_in[12];
    const float* eB1h = (const float*)d_in[13];
    const float* dW1i = (const float*)d_in[14];
    const float* dW1h = (const float*)d_in[15];
    const float* dB1i = (const float*)d_in[16];
    const float* dB1h = (const float*)d_in[17];
    const float* fW0  = (const float*)d_in[18];
    const float* fb0  = (const float*)d_in[19];
    const float* fW1  = (const float*)d_in[20];
    const float* fb1  = (const float*)d_in[21];

    lstm_seq2seq<<<GRID_BLOCKS, NTHREADS>>>(
        src, tgt,
        eW0i, eW0h, eB0i, eB0h,
        dW0i, dW0h, dB0i, dB0h,
        eW1i, eW1h, eB1i, eB1h,
        dW1i, dW1h, dB1i, dB1h,
        fW0, fb0, fW1, fb1,
        (float*)d_out);
}

// round 2
// speedup vs baseline: 1.0372x; 1.0372x over previous
#include <cuda_runtime.h>
#include <math.h>

#define GRID_BLOCKS 128
#define NTHREADS    256
#define Bsz   256
#define Hh    512
#define SRCT  512
#define TGTT  96
#define INMM  64

// ---------------- persistent device scratch (no allocations allowed) ----------------
__device__ float d_H0[2][Bsz * Hh];   // encoder layer0 h ping-pong
__device__ float d_H1[2][Bsz * Hh];   // encoder layer1 h ping-pong
__device__ float d_Hd0[2][Bsz * Hh];  // decoder layer0 h ping-pong (parity 0 = enc final h0)
__device__ float d_Hd1[2][Bsz * Hh];  // decoder layer1 h ping-pong (parity 0 = enc final h1)
__device__ float d_FCA[Bsz * Hh];     // fc hidden activation
__device__ float d_XD[Bsz];           // decoder scalar input
__device__ unsigned g_cnt;            // barrier arrive counter (self-resetting)
__device__ unsigned g_gen;            // barrier generation (monotonic, wrap-safe)

struct __align__(16) SM { float As[64][68]; float Ws[64][68]; };

// ---------------- packed f32x2 FMA (FFMA2 — only reachable via PTX) ----------------
__device__ __forceinline__ unsigned long long ffma2(unsigned long long a,
                                                    unsigned long long b,
                                                    unsigned long long c)
{
    unsigned long long d;
    asm("fma.rn.f32x2 %0, %1, %2, %3;" : "=l"(d) : "l"(a), "l"(b), "l"(c));
    return d;
}
__device__ __forceinline__ float hsum2(unsigned long long v)
{
    float lo, hi;
    asm("mov.b64 {%0, %1}, %2;" : "=f"(lo), "=f"(hi) : "l"(v));
    return lo + hi;
}

// ---------------- grid-wide barrier (all 128 blocks resident) ----------------
__device__ __forceinline__ void grid_sync()
{
    __syncthreads();
    if (threadIdx.x == 0) {
        unsigned gen = *((volatile unsigned*)&g_gen);
        __threadfence();
        if (atomicAdd(&g_cnt, 1u) == GRID_BLOCKS - 1) {
            atomicExch(&g_cnt, 0u);
            __threadfence();
            atomicAdd(&g_gen, 1u);
        } else {
            while (*((volatile unsigned*)&g_gen) == gen) { __nanosleep(64); }
        }
    }
    __syncthreads();
}

// ---------------- 64x64 block GEMM: acc2[bi][gate] += A[64xK] * W[64xK]^T ----------------
// thread (bg,jj): rows bg*4+bi, cols gate*16+jj.  Accumulates in packed f32x2
// (k-even in lo lane, k-odd in hi lane); caller reduces lo+hi.
template <class FA, class FW>
__device__ __forceinline__ void gemm64(SM& s, FA aload, FW wload, int Kpad,
                                       unsigned long long acc2[4][4])
{
    const int tid = threadIdx.x;
    const int bg = tid >> 4, jj = tid & 15;
    #pragma unroll 1
    for (int k0 = 0; k0 < Kpad; k0 += 64) {
        #pragma unroll
        for (int l = 0; l < 16; ++l) {
            int idx = tid + l * 256;
            int r = idx >> 6, k = idx & 63;
            s.As[r][k] = aload(r, k0 + k);
            s.Ws[r][k] = wload(r, k0 + k);
        }
        __syncthreads();
        #pragma unroll
        for (int kk = 0; kk < 64; kk += 4) {
            ulonglong2 a0 = *(const ulonglong2*)&s.As[bg * 4 + 0][kk];
            ulonglong2 a1 = *(const ulonglong2*)&s.As[bg * 4 + 1][kk];
            ulonglong2 a2 = *(const ulonglong2*)&s.As[bg * 4 + 2][kk];
            ulonglong2 a3 = *(const ulonglong2*)&s.As[bg * 4 + 3][kk];
            ulonglong2 w0 = *(const ulonglong2*)&s.Ws[ 0 + jj][kk];
            ulonglong2 w1 = *(const ulonglong2*)&s.Ws[16 + jj][kk];
            ulonglong2 w2 = *(const ulonglong2*)&s.Ws[32 + jj][kk];
            ulonglong2 w3 = *(const ulonglong2*)&s.Ws[48 + jj][kk];
            #define FF2(ACC, A, W) ACC = ffma2(A.x, W.x, ACC); ACC = ffma2(A.y, W.y, ACC);
            FF2(acc2[0][0], a0, w0) FF2(acc2[0][1], a0, w1) FF2(acc2[0][2], a0, w2) FF2(acc2[0][3], a0, w3)
            FF2(acc2[1][0], a1, w0) FF2(acc2[1][1], a1, w1) FF2(acc2[1][2], a1, w2) FF2(acc2[1][3], a1, w3)
            FF2(acc2[2][0], a2, w0) FF2(acc2[2][1], a2, w1) FF2(acc2[2][2], a2, w2) FF2(acc2[2][3], a2, w3)
            FF2(acc2[3][0], a3, w0) FF2(acc2[3][1], a3, w1) FF2(acc2[3][2], a3, w2) FF2(acc2[3][3], a3, w3)
            #undef FF2
        }
        __syncthreads();
    }
}

__device__ __forceinline__ float sigmoidf_(float x) { return 1.f / (1.f + expf(-x)); }

// ---------------- LSTM pointwise cell + h store (c stays in registers) ----------------
__device__ __forceinline__ void cell_store(const unsigned long long acc2[4][4], float creg[4],
                                           const float bias[4],
                                           int b0, int bg, int j,
                                           float* __restrict__ hdst, float* __restrict__ hdst2)
{
    #pragma unroll
    for (int bi = 0; bi < 4; ++bi) {
        float pi = hsum2(acc2[bi][0]) + bias[0];
        float pf = hsum2(acc2[bi][1]) + bias[1];
        float pg = hsum2(acc2[bi][2]) + bias[2];
        float po = hsum2(acc2[bi][3]) + bias[3];
        float ii = sigmoidf_(pi);
        float ff = sigmoidf_(pf);
        float gg = tanhf(pg);
        float oo = sigmoidf_(po);
        float c = ff * creg[bi] + ii * gg;
        creg[bi] = c;
        float h = oo * tanhf(c);
        int b = b0 + bg * 4 + bi;
        hdst[b * Hh + j] = h;
        if (hdst2) hdst2[b * Hh + j] = h;
    }
}

extern "C" __global__ void __launch_bounds__(NTHREADS, 1)
lstm_seq2seq(const float* __restrict__ src, const float* __restrict__ tgt,
             const float* __restrict__ eW0i, const float* __restrict__ eW0h,
             const float* __restrict__ eB0i, const float* __restrict__ eB0h,
             const float* __restrict__ dW0i, const float* __restrict__ dW0h,
             const float* __restrict__ dB0i, const float* __restrict__ dB0h,
             const float* __restrict__ eW1i, const float* __restrict__ eW1h,
             const float* __restrict__ eB1i, const float* __restrict__ eB1h,
             const float* __restrict__ dW1i, const float* __restrict__ dW1h,
             const float* __restrict__ dB1i, const float* __restrict__ dB1h,
             const float* __restrict__ fW0, const float* __restrict__ fb0,
             const float* __restrict__ fW1, const float* __restrict__ fb1,
             float* __restrict__ out)
{
    __shared__ SM s;
    const int tid = threadIdx.x;
    const int blk = blockIdx.x;
    const int jt = blk & 31;   // 32 j-tiles of 16 h-columns
    const int mt = blk >> 5;   // 4 batch tiles of 64
    const int b0 = mt * 64;
    const int bg = tid >> 4, jj = tid & 15;
    const int j = jt * 16 + jj;

    // hoisted per-thread biases (one (gate, j) set per thread)
    float biasE0[4], biasE1[4], biasD0[4], biasD1[4];
    #pragma unroll
    for (int gate = 0; gate < 4; ++gate) {
        int g = gate * Hh + j;
        biasE0[gate] = eB0i[g] + eB0h[g];
        biasE1[gate] = eB1i[g] + eB1h[g];
        biasD0[gate] = dB0i[g] + dB0h[g];
        biasD1[gate] = dB1i[g] + dB1h[g];
    }

    // ---- init: zero h ping-pongs, load decoder x0 ----
    #pragma unroll
    for (int bi = 0; bi < 4; ++bi) {
        int b = b0 + bg * 4 + bi;
        d_H0[0][b * Hh + j] = 0.f; d_H0[1][b * Hh + j] = 0.f;
        d_H1[0][b * Hh + j] = 0.f; d_H1[1][b * Hh + j] = 0.f;
    }
    if (jt == 0 && tid < 64) d_XD[b0 + tid] = tgt[(b0 + tid) * TGTT];

    float cA[4] = {0.f, 0.f, 0.f, 0.f};   // enc0 -> dec0 cell state (same block owns same (b,j))
    float cB[4] = {0.f, 0.f, 0.f, 0.f};   // enc1 -> dec1 cell state
    grid_sync();

    // ================= encoder (wavefront: L0 step t || L1 step t-1) =================
    int p0 = 0, p1 = 0;
    for (int st = 0; st <= SRCT; ++st) {
        if (st < SRCT) {                       // layer 0 at t = st
            const int t = st;
            unsigned long long acc2[4][4] = {};
            const float* Hrd = d_H0[p0];
            auto al = [&](int r, int k) -> float {
                int b = b0 + r;
                if (k < INMM) return __ldg(&src[(size_t)b * SRCT * INMM + t * INMM + k]);
                return __ldcg(&Hrd[b * Hh + (k - INMM)]);
            };
            auto wl = [&](int c, int k) -> float {
                int g = (c >> 4) * Hh + jt * 16 + (c & 15);
                if (k < INMM) return __ldg(&eW0i[g * INMM + k]);
                return __ldg(&eW0h[g * Hh + k - INMM]);
            };
            gemm64(s, al, wl, INMM + Hh, acc2);
            cell_store(acc2, cA, biasE0, b0, bg, j, d_H0[p0 ^ 1],
                       (t == SRCT - 1) ? d_Hd0[0] : (float*)nullptr);
        }
        if (st >= 1) {                         // layer 1 at t = st-1
            const int t = st - 1;
            unsigned long long acc2[4][4] = {};
            const float* Xrd = d_H0[p0];       // enc0 output at t (written last super-step)
            const float* Hrd = d_H1[p1];
            auto al = [&](int r, int k) -> float {
                int b = b0 + r;
                if (k < Hh) return __ldcg(&Xrd[b * Hh + k]);
                return __ldcg(&Hrd[b * Hh + (k - Hh)]);
            };
            auto wl = [&](int c, int k) -> float {
                int g = (c >> 4) * Hh + jt * 16 + (c & 15);
                if (k < Hh) return __ldg(&eW1i[g * Hh + k]);
                return __ldg(&eW1h[g * Hh + k - Hh]);
            };
            gemm64(s, al, wl, 2 * Hh, acc2);
            cell_store(acc2, cB, biasE1, b0, bg, j, d_H1[p1 ^ 1],
                       (t == SRCT - 1) ? d_Hd1[0] : (float*)nullptr);
        }
        grid_sync();
        p0 ^= 1; p1 ^= 1;
    }

    // ================= autoregressive decoder =================
    int pd0 = 0, pd1 = 0;
    for (int t = 0; t < TGTT; ++t) {
        // ---- stage A: decoder layer 0 (input = scalar x) ----
        {
            unsigned long long acc2[4][4] = {};
            const float* Hrd = d_Hd0[pd0];
            auto al = [&](int r, int k) -> float {
                int b = b0 + r;
                if (k == 0) return __ldcg(&d_XD[b]);
                if (k < 513) return __ldcg(&Hrd[b * Hh + k - 1]);
                return 0.f;
            };
            auto wl = [&](int c, int k) -> float {
                int g = (c >> 4) * Hh + jt * 16 + (c & 15);
                if (k == 0) return __ldg(&dW0i[g]);
                if (k < 513) return __ldg(&dW0h[g * Hh + k - 1]);
                return 0.f;
            };
            gemm64(s, al, wl, 576, acc2);
            cell_store(acc2, cA, biasD0, b0, bg, j, d_Hd0[pd0 ^ 1], (float*)nullptr);
        }
        grid_sync(); pd0 ^= 1;

        // ---- stage B: decoder layer 1 ----
        {
            unsigned long long acc2[4][4] = {};
            const float* Xrd = d_Hd0[pd0];     // fresh h0
            const float* Hrd = d_Hd1[pd1];
            auto al = [&](int r, int k) -> float {
                int b = b0 + r;
                if (k < Hh) return __ldcg(&Xrd[b * Hh + k]);
                return __ldcg(&Hrd[b * Hh + k - Hh]);
            };
            auto wl = [&](int c, int k) -> float {
                int g = (c >> 4) * Hh + jt * 16 + (c & 15);
                if (k < Hh) return __ldg(&dW1i[g * Hh + k]);
                return __ldg(&dW1h[g * Hh + k - Hh]);
            };
            gemm64(s, al, wl, 2 * Hh, acc2);
            cell_store(acc2, cB, biasD1, b0, bg, j, d_Hd1[pd1 ^ 1], (float*)nullptr);
        }
        grid_sync(); pd1 ^= 1;

        // ---- stage C: fc hidden = relu(relu(h1) @ W0^T + b0), blocks jt<8 ----
        if (jt < 8) {
            unsigned long long acc2[4][4] = {};
            const float* Hrd = d_Hd1[pd1];
            auto al = [&](int r, int k) -> float {
                float v = __ldcg(&Hrd[(b0 + r) * Hh + k]);
                return v > 0.f ? v : 0.f;
            };
            auto wl = [&](int c, int k) -> float {
                int gc = jt * 64 + c;
                return __ldg(&fW0[gc * Hh + k]);
            };
            gemm64(s, al, wl, Hh, acc2);
            #pragma unroll
            for (int q = 0; q < 4; ++q) {
                int gc = jt * 64 + q * 16 + jj;
                float bb = __ldg(&fb0[gc]);
                #pragma unroll
                for (int bi = 0; bi < 4; ++bi) {
                    float v = hsum2(acc2[bi][q]) + bb;
                    d_FCA[(b0 + bg * 4 + bi) * Hh + gc] = v > 0.f ? v : 0.f;
                }
            }
        }
        grid_sync();

        // ---- stage D: out = a @ W1^T + b1 (scalar), feed back as next x ----
        if (jt == 0) {
            int bb = tid >> 2, q = tid & 3;
            int b = b0 + bb;
            float sum = 0.f;
            for (int k = q * 128; k < q * 128 + 128; k += 4) {
                float4 av = __ldcg((const float4*)&d_FCA[b * Hh + k]);
                float4 wv = *(const float4*)&fW1[k];
                sum += av.x * wv.x + av.y * wv.y + av.z * wv.z + av.w * wv.w;
            }
            sum += __shfl_xor_sync(0xffffffffu, sum, 1);
            sum += __shfl_xor_sync(0xffffffffu, sum, 2);
            if (q == 0) {
                float o = sum + __ldg(&fb1[0]);
                out[b * TGTT + t] = o;
                d_XD[b] = o;
            }
        }
        grid_sync();
    }
}

extern "C" void kernel_launch(void* const* d_in, const int* in_sizes, int n_in,
                              void* d_out, int out_size)
{
    const float* src  = (const float*)d_in[0];
    const float* tgt  = (const float*)d_in[1];
    const float* eW0i = (const float*)d_in[2];
    const float* eW0h = (const float*)d_in[3];
    const float* eB0i = (const float*)d_in[4];
    const float* eB0h = (const float*)d_in[5];
    const float* dW0i = (const float*)d_in[6];
    const float* dW0h = (const float*)d_in[7];
    const float* dB0i = (const float*)d_in[8];
    const float* dB0h = (const float*)d_in[9];
    const float* eW1i = (const float*)d_in[10];
    const float* eW1h = (const float*)d_in[11];
    const float* eB1i = (const float*)d_in[12];
    const float* eB1h = (const float*)d_in[13];
    const float* dW1i = (const float*)d_in[14];
    const float* dW1h = (const float*)d_in[15];
    const float* dB1i = (const float*)d_in[16];
    const float* dB1h = (const float*)d_in[17];
    const float* fW0  = (const float*)d_in[18];
    const float* fb0  = (const float*)d_in[19];
    const float* fW1  = (const float*)d_in[20];
    const float* fb1  = (const float*)d_in[21];

    lstm_seq2seq<<<GRID_BLOCKS, NTHREADS>>>(
        src, tgt,
        eW0i, eW0h, eB0i, eB0h,
        dW0i, dW0h, dB0i, dB0h,
        eW1i, eW1h, eB1i, eB1h,
        dW1i, dW1h, dB1i, dB1h,
        fW0, fb0, fW1, fb1,
        (float*)d_out);
}

// round 5
// speedup vs baseline: 2.4512x; 2.3633x over previous
#include <cuda_runtime.h>
#include <cuda_bf16.h>
#include <stdint.h>
#include <math.h>

#define GRID_BLOCKS 128
#define NTHREADS    256
#define Bsz   256
#define Hh    512
#define SRCT  512
#define TGTT  96
#define INMM  64

// ---------------- persistent device scratch (no allocations allowed) ----------------
__device__ float d_H0[2][Bsz * Hh];
__device__ float d_H1[2][Bsz * Hh];
__device__ float d_Hd0[2][Bsz * Hh];
__device__ float d_Hd1[2][Bsz * Hh];
__device__ float d_FCA[Bsz * Hh];
__device__ float d_XD[Bsz];
__device__ unsigned g_cnt;
__device__ unsigned g_gen;

// bf16 hi/lo split weight planes, built by prep kernel each run.
// Layout: row-major [n][K] with K the concatenated input dim.
__device__ __nv_bfloat16 g_eW0[2][2048 * 576];   // enc0: [src(64) | h(512)]
__device__ __nv_bfloat16 g_eW1[2][2048 * 1024];  // enc1: [h0(512) | h1(512)]
__device__ __nv_bfloat16 g_dW0[2][2048 * 512];   // dec0: [h(512)]  (x column folded into epilogue)
__device__ __nv_bfloat16 g_dW1[2][2048 * 1024];  // dec1: [h0(512) | h1(512)]
__device__ __nv_bfloat16 g_fW0[2][512 * 512];    // fc0

// ---------------- shared memory ----------------
struct __align__(16) SMt {
    union {
        struct {
            __nv_bfloat16 Ahi[64][72];
            __nv_bfloat16 Alo[64][72];
            __nv_bfloat16 Whi[64][72];
            __nv_bfloat16 Wlo[64][72];
        } st;
        float epi[64][68];
    };
};

// ---------------- grid-wide barrier ----------------
__device__ __forceinline__ void grid_sync()
{
    __syncthreads();
    if (threadIdx.x == 0) {
        unsigned gen = *((volatile unsigned*)&g_gen);
        __threadfence();
        if (atomicAdd(&g_cnt, 1u) == GRID_BLOCKS - 1) {
            atomicExch(&g_cnt, 0u);
            __threadfence();
            atomicAdd(&g_gen, 1u);
        } else {
            while (*((volatile unsigned*)&g_gen) == gen) { __nanosleep(64); }
        }
    }
    __syncthreads();
}

// ---------------- tensor-core primitives ----------------
__device__ __forceinline__ void ldsm4(uint32_t r[4], uint32_t a)
{
    asm volatile("ldmatrix.sync.aligned.m8n8.x4.shared.b16 {%0,%1,%2,%3}, [%4];"
                 : "=r"(r[0]), "=r"(r[1]), "=r"(r[2]), "=r"(r[3]) : "r"(a));
}
__device__ __forceinline__ void mma16816(float c[4], const uint32_t a[4], uint32_t b0, uint32_t b1)
{
    asm volatile("mma.sync.aligned.m16n8k16.row.col.f32.bf16.bf16.f32 "
                 "{%0,%1,%2,%3},{%4,%5,%6,%7},{%8,%9},{%0,%1,%2,%3};"
                 : "+f"(c[0]), "+f"(c[1]), "+f"(c[2]), "+f"(c[3])
                 : "r"(a[0]), "r"(a[1]), "r"(a[2]), "r"(a[3]), "r"(b0), "r"(b1));
}

__device__ __forceinline__ void mma_stage(uint32_t sAhi, uint32_t sAlo, uint32_t sWhi, uint32_t sWlo,
                                          float acc[2][2][4])
{
    const int tid = threadIdx.x, lane = tid & 31, wid = tid >> 5;
    const int wm = wid >> 2, wn = wid & 3;
    const int arow = wm * 32 + (lane & 15);
    const int acol = (lane >> 4) * 8;
    const int wrow = wn * 16 + (lane & 7) + (lane >> 4) * 8;
    const int wcol = ((lane >> 3) & 1) * 8;
    #pragma unroll
    for (int kk = 0; kk < 64; kk += 16) {
        uint32_t wh[4], wl[4], ah[2][4], al[2][4];
        ldsm4(wh, sWhi + (wrow * 72 + kk + wcol) * 2);
        ldsm4(wl, sWlo + (wrow * 72 + kk + wcol) * 2);
        #pragma unroll
        for (int mi = 0; mi < 2; ++mi) {
            ldsm4(ah[mi], sAhi + ((arow + mi * 16) * 72 + kk + acol) * 2);
            ldsm4(al[mi], sAlo + ((arow + mi * 16) * 72 + kk + acol) * 2);
        }
        #pragma unroll
        for (int mi = 0; mi < 2; ++mi)
            #pragma unroll
            for (int ni = 0; ni < 2; ++ni) {
                mma16816(acc[mi][ni], ah[mi], wh[ni * 2], wh[ni * 2 + 1]);
                mma16816(acc[mi][ni], ah[mi], wl[ni * 2], wl[ni * 2 + 1]);
                mma16816(acc[mi][ni], al[mi], wh[ni * 2], wh[ni * 2 + 1]);
            }
    }
}

// ---------------- 64x64 bf16x3 GEMM with register prefetch pipeline ----------------
// getA(s, p, stride): fp32 A row base (already offset by b0) + row stride for stage s
// gwhi/gwlo(n): bf16 row pointer (k=0) for local output column n
template <class GA, class GWH, class GWL>
__device__ __forceinline__ void tgemm(SMt& sm, int S, GA getA, GWH gwhi, GWL gwlo,
                                      bool relu, float acc[2][2][4])
{
    const int tid = threadIdx.x;
    #pragma unroll
    for (int mi = 0; mi < 2; ++mi)
        #pragma unroll
        for (int ni = 0; ni < 2; ++ni)
            #pragma unroll
            for (int q = 0; q < 4; ++q) acc[mi][ni][q] = 0.f;

    const uint32_t sAhi = (uint32_t)__cvta_generic_to_shared(&sm.st.Ahi[0][0]);
    const uint32_t sAlo = (uint32_t)__cvta_generic_to_shared(&sm.st.Alo[0][0]);
    const uint32_t sWhi = (uint32_t)__cvta_generic_to_shared(&sm.st.Whi[0][0]);
    const uint32_t sWlo = (uint32_t)__cvta_generic_to_shared(&sm.st.Wlo[0][0]);

    float4 av[4];
    uint4  wh[2], wl[2];

    auto fetch = [&](int s) {
        const float* ap; int astr;
        getA(s, ap, astr);
        #pragma unroll
        for (int l = 0; l < 4; ++l) {
            int lin = tid + l * 256, r = lin >> 4, kq = lin & 15;
            av[l] = __ldcg((const float4*)(ap + (size_t)r * astr + kq * 4));
        }
        int koff = s * 64;
        #pragma unroll
        for (int l = 0; l < 2; ++l) {
            int lin = tid + l * 256, r = lin >> 3, seg = lin & 7;
            wh[l] = *(const uint4*)(gwhi(r) + koff + seg * 8);
            wl[l] = *(const uint4*)(gwlo(r) + koff + seg * 8);
        }
    };

    __syncthreads();           // smem free of previous epilogue readers
    fetch(0);
    for (int s = 0; s < S; ++s) {
        // ---- store staged regs to smem (split A on the fly) ----
        #pragma unroll
        for (int l = 0; l < 2; ++l) {
            int lin = tid + l * 256, r = lin >> 3, seg = lin & 7;
            *(uint4*)&sm.st.Whi[r][seg * 8] = wh[l];
            *(uint4*)&sm.st.Wlo[r][seg * 8] = wl[l];
        }
        #pragma unroll
        for (int l = 0; l < 4; ++l) {
            int lin = tid + l * 256, r = lin >> 4, kq = lin & 15;
            float4 v = av[l];
            if (relu) { v.x = fmaxf(v.x, 0.f); v.y = fmaxf(v.y, 0.f); v.z = fmaxf(v.z, 0.f); v.w = fmaxf(v.w, 0.f); }
            __nv_bfloat162 h01, h23, l01, l23;
            h01.x = __float2bfloat16_rn(v.x); h01.y = __float2bfloat16_rn(v.y);
            h23.x = __float2bfloat16_rn(v.z); h23.y = __float2bfloat16_rn(v.w);
            l01.x = __float2bfloat16_rn(v.x - __bfloat162float(h01.x));
            l01.y = __float2bfloat16_rn(v.y - __bfloat162float(h01.y));
            l23.x = __float2bfloat16_rn(v.z - __bfloat162float(h23.x));
            l23.y = __float2bfloat16_rn(v.w - __bfloat162float(h23.y));
            *(__nv_bfloat162*)&sm.st.Ahi[r][kq * 4]     = h01;
            *(__nv_bfloat162*)&sm.st.Ahi[r][kq * 4 + 2] = h23;
            *(__nv_bfloat162*)&sm.st.Alo[r][kq * 4]     = l01;
            *(__nv_bfloat162*)&sm.st.Alo[r][kq * 4 + 2] = l23;
        }
        if (s + 1 < S) fetch(s + 1);   // LDGs overlap with mma below
        __syncthreads();
        mma_stage(sAhi, sAlo, sWhi, sWlo, acc);
        __syncthreads();
    }

    // ---- epilogue: fragments -> sm.epi ----
    const int lane = tid & 31, wid = tid >> 5;
    const int wm = wid >> 2, wn = wid & 3;
    #pragma unroll
    for (int mi = 0; mi < 2; ++mi)
        #pragma unroll
        for (int ni = 0; ni < 2; ++ni) {
            int r = wm * 32 + mi * 16 + (lane >> 2);
            int c = wn * 16 + ni * 8 + (lane & 3) * 2;
            *(float2*)&sm.epi[r][c]     = make_float2(acc[mi][ni][0], acc[mi][ni][1]);
            *(float2*)&sm.epi[r + 8][c] = make_float2(acc[mi][ni][2], acc[mi][ni][3]);
        }
    __syncthreads();
}

__device__ __forceinline__ float sigmoidf_(float x) { return 1.f / (1.f + expf(-x)); }

// ---------------- LSTM pointwise cell from epi smem (c in registers) ----------------
__device__ __forceinline__ void cell_epi(const SMt& sm, float creg[4], const float bias[4],
                                         int b0, int bg, int jj, int j,
                                         float* __restrict__ hdst, float* __restrict__ hdst2,
                                         const float* xv, const float* dwi)
{
    #pragma unroll
    for (int bi = 0; bi < 4; ++bi) {
        float pre[4];
        #pragma unroll
        for (int g = 0; g < 4; ++g) {
            pre[g] = sm.epi[bg * 4 + bi][g * 16 + jj] + bias[g];
            if (xv) pre[g] += xv[bi] * dwi[g];
        }
        float ii = sigmoidf_(pre[0]);
        float ff = sigmoidf_(pre[1]);
        float gg = tanhf(pre[2]);
        float oo = sigmoidf_(pre[3]);
        float c = ff * creg[bi] + ii * gg;
        creg[bi] = c;
        float h = oo * tanhf(c);
        int b = b0 + bg * 4 + bi;
        hdst[b * Hh + j] = h;
        if (hdst2) hdst2[b * Hh + j] = h;
    }
}

// ---------------- prologue: split weights into bf16 hi/lo planes ----------------
__global__ void prep_weights(const float* __restrict__ eW0i, const float* __restrict__ eW0h,
                             const float* __restrict__ eW1i, const float* __restrict__ eW1h,
                             const float* __restrict__ dW0h,
                             const float* __restrict__ dW1i, const float* __restrict__ dW1h,
                             const float* __restrict__ fW0)
{
    const long N0 = 2048L * 576;
    const long N1 = N0 + 2048L * 1024;
    const long N2 = N1 + 2048L * 512;
    const long N3 = N2 + 2048L * 1024;
    const long N4 = N3 + 512L * 512;
    for (long idx = blockIdx.x * (long)blockDim.x + threadIdx.x; idx < N4;
         idx += (long)gridDim.x * blockDim.x) {
        float x; __nv_bfloat16 *hp, *lp;
        if (idx < N0) {
            long j = idx; int n = (int)(j / 576), k = (int)(j % 576);
            x = (k < 64) ? eW0i[n * 64 + k] : eW0h[n * 512 + k - 64];
            hp = &g_eW0[0][j]; lp = &g_eW0[1][j];
        } else if (idx < N1) {
            long j = idx - N0; int n = (int)(j / 1024), k = (int)(j % 1024);
            x = (k < 512) ? eW1i[n * 512 + k] : eW1h[n * 512 + k - 512];
            hp = &g_eW1[0][j]; lp = &g_eW1[1][j];
        } else if (idx < N2) {
            long j = idx - N1;
            x = dW0h[j];
            hp = &g_dW0[0][j]; lp = &g_dW0[1][j];
        } else if (idx < N3) {
            long j = idx - N2; int n = (int)(j / 1024), k = (int)(j % 1024);
            x = (k < 512) ? dW1i[n * 512 + k] : dW1h[n * 512 + k - 512];
            hp = &g_dW1[0][j]; lp = &g_dW1[1][j];
        } else {
            long j = idx - N3;
            x = fW0[j];
            hp = &g_fW0[0][j]; lp = &g_fW0[1][j];
        }
        __nv_bfloat16 hi = __float2bfloat16_rn(x);
        *hp = hi;
        *lp = __float2bfloat16_rn(x - __bfloat162float(hi));
    }
}

extern "C" __global__ void __launch_bounds__(NTHREADS, 1)
lstm_seq2seq(const float* __restrict__ src, const float* __restrict__ tgt,
             const float* __restrict__ eB0i, const float* __restrict__ eB0h,
             const float* __restrict__ dW0i,
             const float* __restrict__ dB0i, const float* __restrict__ dB0h,
             const float* __restrict__ eB1i, const float* __restrict__ eB1h,
             const float* __restrict__ dB1i, const float* __restrict__ dB1h,
             const float* __restrict__ fb0,
             const float* __restrict__ fW1, const float* __restrict__ fb1,
             float* __restrict__ out)
{
    __shared__ SMt sm;
    const int tid = threadIdx.x;
    const int blk = blockIdx.x;
    const int jt = blk & 31;   // 32 j-tiles of 16 h-columns
    const int mt = blk >> 5;   // 4 batch tiles of 64
    const int b0 = mt * 64;
    const int bg = tid >> 4, jj = tid & 15;
    const int j = jt * 16 + jj;
    const int jbase = jt * 16;

    float biasE0[4], biasE1[4], biasD0[4], biasD1[4], dwi[4];
    #pragma unroll
    for (int gate = 0; gate < 4; ++gate) {
        int g = gate * Hh + j;
        biasE0[gate] = eB0i[g] + eB0h[g];
        biasE1[gate] = eB1i[g] + eB1h[g];
        biasD0[gate] = dB0i[g] + dB0h[g];
        biasD1[gate] = dB1i[g] + dB1h[g];
        dwi[gate]    = dW0i[g];
    }

    #pragma unroll
    for (int bi = 0; bi < 4; ++bi) {
        int b = b0 + bg * 4 + bi;
        d_H0[0][b * Hh + j] = 0.f; d_H0[1][b * Hh + j] = 0.f;
        d_H1[0][b * Hh + j] = 0.f; d_H1[1][b * Hh + j] = 0.f;
    }
    if (jt == 0 && tid < 64) d_XD[b0 + tid] = tgt[(b0 + tid) * TGTT];

    float cA[4] = {0.f, 0.f, 0.f, 0.f};
    float cB[4] = {0.f, 0.f, 0.f, 0.f};
    float acc[2][2][4];
    grid_sync();

    // weight row mappers for this block's 64 output columns (n = gate*16 + col)
    auto wr_lstm = [&](const __nv_bfloat16* plane, int K, int n) -> const __nv_bfloat16* {
        int g = (n >> 4) * Hh + jbase + (n & 15);
        return plane + (size_t)g * K;
    };

    // ================= encoder (wavefront: L0 step t || L1 step t-1) =================
    int p0 = 0, p1 = 0;
    for (int st = 0; st <= SRCT; ++st) {
        if (st < SRCT) {                       // layer 0 at t = st
            const int t = st;
            const float* Hrd = d_H0[p0];
            auto ga = [&](int s, const float*& p, int& str) {
                if (s == 0) { p = src + (size_t)b0 * SRCT * INMM + t * INMM; str = SRCT * INMM; }
                else        { p = Hrd + b0 * Hh + (s - 1) * 64;              str = Hh; }
            };
            auto gh = [&](int n) { return wr_lstm(g_eW0[0], 576, n); };
            auto gl = [&](int n) { return wr_lstm(g_eW0[1], 576, n); };
            tgemm(sm, 9, ga, gh, gl, false, acc);
            cell_epi(sm, cA, biasE0, b0, bg, jj, j, d_H0[p0 ^ 1],
                     (t == SRCT - 1) ? d_Hd0[0] : (float*)nullptr, nullptr, nullptr);
        }
        if (st >= 1) {                         // layer 1 at t = st-1
            const int t = st - 1;
            const float* Xrd = d_H0[p0];
            const float* Hrd = d_H1[p1];
            auto ga = [&](int s, const float*& p, int& str) {
                if (s < 8) { p = Xrd + b0 * Hh + s * 64;       str = Hh; }
                else       { p = Hrd + b0 * Hh + (s - 8) * 64; str = Hh; }
            };
            auto gh = [&](int n) { return wr_lstm(g_eW1[0], 1024, n); };
            auto gl = [&](int n) { return wr_lstm(g_eW1[1], 1024, n); };
            tgemm(sm, 16, ga, gh, gl, false, acc);
            cell_epi(sm, cB, biasE1, b0, bg, jj, j, d_H1[p1 ^ 1],
                     (t == SRCT - 1) ? d_Hd1[0] : (float*)nullptr, nullptr, nullptr);
        }
        grid_sync();
        p0 ^= 1; p1 ^= 1;
    }

    // ================= autoregressive decoder =================
    int pd0 = 0, pd1 = 0;
    for (int t = 0; t < TGTT; ++t) {
        // ---- stage A: decoder layer 0 (h GEMM + rank-1 x term in epilogue) ----
        {
            const float* Hrd = d_Hd0[pd0];
            auto ga = [&](int s, const float*& p, int& str) {
                p = Hrd + b0 * Hh + s * 64; str = Hh;
            };
            auto gh = [&](int n) { return wr_lstm(g_dW0[0], 512, n); };
            auto gl = [&](int n) { return wr_lstm(g_dW0[1], 512, n); };
            tgemm(sm, 8, ga, gh, gl, false, acc);
            float xv[4];
            #pragma unroll
            for (int bi = 0; bi < 4; ++bi) xv[bi] = __ldcg(&d_XD[b0 + bg * 4 + bi]);
            cell_epi(sm, cA, biasD0, b0, bg, jj, j, d_Hd0[pd0 ^ 1], (float*)nullptr, xv, dwi);
        }
        grid_sync(); pd0 ^= 1;

        // ---- stage B: decoder layer 1 ----
        {
            const float* Xrd = d_Hd0[pd0];
            const float* Hrd = d_Hd1[pd1];
            auto ga = [&](int s, const float*& p, int& str) {
                if (s < 8) { p = Xrd + b0 * Hh + s * 64;       str = Hh; }
                else       { p = Hrd + b0 * Hh + (s - 8) * 64; str = Hh; }
            };
            auto gh = [&](int n) { return wr_lstm(g_dW1[0], 1024, n); };
            auto gl = [&](int n) { return wr_lstm(g_dW1[1], 1024, n); };
            tgemm(sm, 16, ga, gh, gl, false, acc);
            cell_epi(sm, cB, biasD1, b0, bg, jj, j, d_Hd1[pd1 ^ 1], (float*)nullptr, nullptr, nullptr);
        }
        grid_sync(); pd1 ^= 1;

        // ---- stage C: fc hidden = relu(relu(h1) @ W0^T + b0), blocks jt<8 ----
        if (jt < 8) {
            const float* Hrd = d_Hd1[pd1];
            auto ga = [&](int s, const float*& p, int& str) {
                p = Hrd + b0 * Hh + s * 64; str = Hh;
            };
            auto gh = [&](int n) -> const __nv_bfloat16* { return g_fW0[0] + (size_t)(jt * 64 + n) * 512; };
            auto gl = [&](int n) -> const __nv_bfloat16* { return g_fW0[1] + (size_t)(jt * 64 + n) * 512; };
            tgemm(sm, 8, ga, gh, gl, true, acc);
            #pragma unroll
            for (int q = 0; q < 4; ++q) {
                int gc = jt * 64 + q * 16 + jj;
                float bb = __ldg(&fb0[gc]);
                #pragma unroll
                for (int bi = 0; bi < 4; ++bi) {
                    float v = sm.epi[bg * 4 + bi][q * 16 + jj] + bb;
                    d_FCA[(b0 + bg * 4 + bi) * Hh + gc] = v > 0.f ? v : 0.f;
                }
            }
        }
        grid_sync();

        // ---- stage D: out = a @ W1^T + b1 (scalar), feed back as next x ----
        if (jt == 0) {
            int bb = tid >> 2, q = tid & 3;
            int b = b0 + bb;
            float sum = 0.f;
            for (int k = q * 128; k < q * 128 + 128; k += 4) {
                float4 av = __ldcg((const float4*)&d_FCA[b * Hh + k]);
                float4 wv = *(const float4*)&fW1[k];
                sum += av.x * wv.x + av.y * wv.y + av.z * wv.z + av.w * wv.w;
            }
            sum += __shfl_xor_sync(0xffffffffu, sum, 1);
            sum += __shfl_xor_sync(0xffffffffu, sum, 2);
            if (q == 0) {
                float o = sum + __ldg(&fb1[0]);
                out[b * TGTT + t] = o;
                d_XD[b] = o;
            }
        }
        grid_sync();
    }
}

extern "C" void kernel_launch(void* const* d_in, const int* in_sizes, int n_in,
                              void* d_out, int out_size)
{
    const float* src  = (const float*)d_in[0];
    const float* tgt  = (const float*)d_in[1];
    const float* eW0i = (const float*)d_in[2];
    const float* eW0h = (const float*)d_in[3];
    const float* eB0i = (const float*)d_in[4];
    const float* eB0h = (const float*)d_in[5];
    const float* dW0i = (const float*)d_in[6];
    const float* dW0h = (const float*)d_in[7];
    const float* dB0i = (const float*)d_in[8];
    const float* dB0h = (const float*)d_in[9];
    const float* eW1i = (const float*)d_in[10];
    const float* eW1h = (const float*)d_in[11];
    const float* eB1i = (const float*)d_in[12];
    const float* eB1h = (const float*)d_in[13];
    const float* dW1i = (const float*)d_in[14];
    const float* dW1h = (const float*)d_in[15];
    const float* dB1i = (const float*)d_in[16];
    const float* dB1h = (const float*)d_in[17];
    const float* fW0  = (const float*)d_in[18];
    const float* fb0  = (const float*)d_in[19];
    const float* fW1  = (const float*)d_in[20];
    const float* fb1  = (const float*)d_in[21];

    prep_weights<<<512, 256>>>(eW0i, eW0h, eW1i, eW1h, dW0h, dW1i, dW1h, fW0);

    lstm_seq2seq<<<GRID_BLOCKS, NTHREADS>>>(
        src, tgt,
        eB0i, eB0h,
        dW0i, dB0i, dB0h,
        eB1i, eB1h,
        dB1i, dB1h,
        fb0, fW1, fb1,
        (float*)d_out);
}

// round 6
// speedup vs baseline: 2.5745x; 1.0503x over previous
#include <cuda_runtime.h>
#include <cuda_bf16.h>
#include <stdint.h>
#include <math.h>

#define GRID_BLOCKS 128
#define NTHREADS    256
#define Bsz   256
#define Hh    512
#define SRCT  512
#define TGTT  96
#define INMM  64

// ---------------- persistent device scratch (no allocations allowed) ----------------
__device__ float d_FCA[Bsz * Hh];     // fc hidden activation (fp32)
__device__ float d_XD[Bsz];           // decoder scalar input
__device__ unsigned g_cnt;
__device__ unsigned g_gen;

// h state as bf16 hi/lo planes: [pingpong][plane][b*Hh + j]
__device__ __nv_bfloat16 hH0[2][2][Bsz * Hh];
__device__ __nv_bfloat16 hH1[2][2][Bsz * Hh];
__device__ __nv_bfloat16 hHd0[2][2][Bsz * Hh];
__device__ __nv_bfloat16 hHd1[2][2][Bsz * Hh];
__device__ __nv_bfloat16 d_FCr[2][Bsz * Hh];          // relu(h1) planes for fc
__device__ __nv_bfloat16 g_srcs[2][Bsz * SRCT * INMM]; // split src

// bf16 hi/lo split weight planes (prep kernel). Row-major [n][K].
__device__ __nv_bfloat16 g_eW0[2][2048 * 576];
__device__ __nv_bfloat16 g_eW1[2][2048 * 1024];
__device__ __nv_bfloat16 g_dW0[2][2048 * 512];
__device__ __nv_bfloat16 g_dW1[2][2048 * 1024];
__device__ __nv_bfloat16 g_fW0[2][512 * 512];

// ---------------- shared memory ----------------
struct __align__(16) Planes {
    __nv_bfloat16 Ahi[64][72];
    __nv_bfloat16 Alo[64][72];
    __nv_bfloat16 Whi[64][72];
    __nv_bfloat16 Wlo[64][72];
};
struct __align__(16) SMt {
    union { Planes buf[2]; float epi[64][68]; };
};
#define OFF_ALO  9216
#define OFF_WHI 18432
#define OFF_WLO 27648

// ---------------- grid-wide barrier ----------------
__device__ __forceinline__ void grid_sync()
{
    __syncthreads();
    if (threadIdx.x == 0) {
        unsigned gen = *((volatile unsigned*)&g_gen);
        __threadfence();
        if (atomicAdd(&g_cnt, 1u) == GRID_BLOCKS - 1) {
            atomicExch(&g_cnt, 0u);
            __threadfence();
            atomicAdd(&g_gen, 1u);
        } else {
            while (*((volatile unsigned*)&g_gen) == gen) { __nanosleep(64); }
        }
    }
    __syncthreads();
}

// ---------------- tensor-core primitives ----------------
__device__ __forceinline__ void ldsm4(uint32_t r[4], uint32_t a)
{
    asm volatile("ldmatrix.sync.aligned.m8n8.x4.shared.b16 {%0,%1,%2,%3}, [%4];"
                 : "=r"(r[0]), "=r"(r[1]), "=r"(r[2]), "=r"(r[3]) : "r"(a));
}
__device__ __forceinline__ void mma16816(float c[4], const uint32_t a[4], uint32_t b0, uint32_t b1)
{
    asm volatile("mma.sync.aligned.m16n8k16.row.col.f32.bf16.bf16.f32 "
                 "{%0,%1,%2,%3},{%4,%5,%6,%7},{%8,%9},{%0,%1,%2,%3};"
                 : "+f"(c[0]), "+f"(c[1]), "+f"(c[2]), "+f"(c[3])
                 : "r"(a[0]), "r"(a[1]), "r"(a[2]), "r"(a[3]), "r"(b0), "r"(b1));
}

__device__ __forceinline__ void mma_stage(uint32_t base, float acc[2][2][4])
{
    const int tid = threadIdx.x, lane = tid & 31, wid = tid >> 5;
    const int wm = wid >> 2, wn = wid & 3;
    const int arow = wm * 32 + (lane & 15);
    const int acol = (lane >> 4) * 8;
    const int wrow = wn * 16 + (lane & 7) + (lane >> 4) * 8;
    const int wcol = ((lane >> 3) & 1) * 8;
    const uint32_t sAhi = base, sAlo = base + OFF_ALO, sWhi = base + OFF_WHI, sWlo = base + OFF_WLO;
    #pragma unroll
    for (int kk = 0; kk < 64; kk += 16) {
        uint32_t wh[4], wl[4], ah[2][4], al[2][4];
        ldsm4(wh, sWhi + (wrow * 72 + kk + wcol) * 2);
        ldsm4(wl, sWlo + (wrow * 72 + kk + wcol) * 2);
        #pragma unroll
        for (int mi = 0; mi < 2; ++mi) {
            ldsm4(ah[mi], sAhi + ((arow + mi * 16) * 72 + kk + acol) * 2);
            ldsm4(al[mi], sAlo + ((arow + mi * 16) * 72 + kk + acol) * 2);
        }
        #pragma unroll
        for (int mi = 0; mi < 2; ++mi)
            #pragma unroll
            for (int ni = 0; ni < 2; ++ni) {
                mma16816(acc[mi][ni], ah[mi], wh[ni * 2], wh[ni * 2 + 1]);
                mma16816(acc[mi][ni], ah[mi], wl[ni * 2], wl[ni * 2 + 1]);
                mma16816(acc[mi][ni], al[mi], wh[ni * 2], wh[ni * 2 + 1]);
            }
    }
}

// ---------------- 64x64 bf16x3 GEMM, double-buffered + pipelined ----------------
// gah/gal(s,r): bf16 row pointer (chunk s, A-row r) for hi/lo plane
// gwh/gwl(s,r): bf16 row pointer (chunk s, local output col r) for hi/lo plane
template <class GAH, class GAL, class GWH, class GWL>
__device__ __forceinline__ void tgemm(SMt& sm, int S, GAH gah, GAL gal, GWH gwh, GWL gwl,
                                      float acc[2][2][4])
{
    const int tid = threadIdx.x;
    #pragma unroll
    for (int mi = 0; mi < 2; ++mi)
        #pragma unroll
        for (int ni = 0; ni < 2; ++ni)
            #pragma unroll
            for (int q = 0; q < 4; ++q) acc[mi][ni][q] = 0.f;

    const uint32_t base0 = (uint32_t)__cvta_generic_to_shared(&sm.buf[0]);
    const uint32_t base1 = (uint32_t)__cvta_generic_to_shared(&sm.buf[1]);
    const int r0 = tid >> 3, seg8 = (tid & 7) * 8;
    const int r1 = r0 + 32;

    uint4 ra[4], rw[4];
    auto fetch = [&](int s) {
        ra[0] = __ldcg((const uint4*)(gah(s, r0) + seg8));
        ra[1] = __ldcg((const uint4*)(gah(s, r1) + seg8));
        ra[2] = __ldcg((const uint4*)(gal(s, r0) + seg8));
        ra[3] = __ldcg((const uint4*)(gal(s, r1) + seg8));
        rw[0] = *(const uint4*)(gwh(s, r0) + seg8);
        rw[1] = *(const uint4*)(gwh(s, r1) + seg8);
        rw[2] = *(const uint4*)(gwl(s, r0) + seg8);
        rw[3] = *(const uint4*)(gwl(s, r1) + seg8);
    };
    auto stow = [&](Planes& P) {
        *(uint4*)&P.Ahi[r0][seg8] = ra[0];
        *(uint4*)&P.Ahi[r1][seg8] = ra[1];
        *(uint4*)&P.Alo[r0][seg8] = ra[2];
        *(uint4*)&P.Alo[r1][seg8] = ra[3];
        *(uint4*)&P.Whi[r0][seg8] = rw[0];
        *(uint4*)&P.Whi[r1][seg8] = rw[1];
        *(uint4*)&P.Wlo[r0][seg8] = rw[2];
        *(uint4*)&P.Wlo[r1][seg8] = rw[3];
    };

    fetch(0);
    __syncthreads();          // prior epi readers / prior buffers done
    stow(sm.buf[0]);
    if (S > 1) fetch(1);
    __syncthreads();          // buf0 visible
    for (int s = 0; s < S; ++s) {
        if (s + 1 < S) stow(sm.buf[(s + 1) & 1]);  // STS to idle buffer
        if (s + 2 < S) fetch(s + 2);               // LDG next-next
        mma_stage((s & 1) ? base1 : base0, acc);   // ldsm + hmma on ready buffer
        __syncthreads();
    }

    // ---- epilogue: fragments -> sm.epi ----
    const int lane = tid & 31, wid = tid >> 5;
    const int wm = wid >> 2, wn = wid & 3;
    #pragma unroll
    for (int mi = 0; mi < 2; ++mi)
        #pragma unroll
        for (int ni = 0; ni < 2; ++ni) {
            int r = wm * 32 + mi * 16 + (lane >> 2);
            int c = wn * 16 + ni * 8 + (lane & 3) * 2;
            *(float2*)&sm.epi[r][c]     = make_float2(acc[mi][ni][0], acc[mi][ni][1]);
            *(float2*)&sm.epi[r + 8][c] = make_float2(acc[mi][ni][2], acc[mi][ni][3]);
        }
    __syncthreads();
}

__device__ __forceinline__ float sigmoidf_(float x) { return 1.f / (1.f + expf(-x)); }

// ---------------- LSTM pointwise cell: epi smem -> split h planes ----------------
__device__ __forceinline__ void cell_epi(const SMt& sm, float creg[4], const float bias[4],
                                         int b0, int bg, int jj, int j,
                                         __nv_bfloat16* __restrict__ hh, __nv_bfloat16* __restrict__ hl,
                                         __nv_bfloat16* __restrict__ h2h, __nv_bfloat16* __restrict__ h2l,
                                         __nv_bfloat16* __restrict__ rh, __nv_bfloat16* __restrict__ rl,
                                         const float* xv, const float* dwi)
{
    #pragma unroll
    for (int bi = 0; bi < 4; ++bi) {
        float pre[4];
        #pragma unroll
        for (int g = 0; g < 4; ++g) {
            pre[g] = sm.epi[bg * 4 + bi][g * 16 + jj] + bias[g];
            if (xv) pre[g] += xv[bi] * dwi[g];
        }
        float ii = sigmoidf_(pre[0]);
        float ff = sigmoidf_(pre[1]);
        float gg = tanhf(pre[2]);
        float oo = sigmoidf_(pre[3]);
        float c = ff * creg[bi] + ii * gg;
        creg[bi] = c;
        float h = oo * tanhf(c);
        int idx = (b0 + bg * 4 + bi) * Hh + j;
        __nv_bfloat16 hi = __float2bfloat16_rn(h);
        __nv_bfloat16 lo = __float2bfloat16_rn(h - __bfloat162float(hi));
        hh[idx] = hi; hl[idx] = lo;
        if (h2h) { h2h[idx] = hi; h2l[idx] = lo; }
        if (rh) {
            float rv = fmaxf(h, 0.f);
            __nv_bfloat16 rhi = __float2bfloat16_rn(rv);
            rh[idx] = rhi;
            rl[idx] = __float2bfloat16_rn(rv - __bfloat162float(rhi));
        }
    }
}

// ---------------- prologue: split weights + src into bf16 hi/lo planes ----------------
__global__ void prep_weights(const float* __restrict__ src,
                             const float* __restrict__ eW0i, const float* __restrict__ eW0h,
                             const float* __restrict__ eW1i, const float* __restrict__ eW1h,
                             const float* __restrict__ dW0h,
                             const float* __restrict__ dW1i, const float* __restrict__ dW1h,
                             const float* __restrict__ fW0)
{
    const long NS = (long)Bsz * SRCT * INMM;
    const long N0 = NS + 2048L * 576;
    const long N1 = N0 + 2048L * 1024;
    const long N2 = N1 + 2048L * 512;
    const long N3 = N2 + 2048L * 1024;
    const long N4 = N3 + 512L * 512;
    for (long idx = blockIdx.x * (long)blockDim.x + threadIdx.x; idx < N4;
         idx += (long)gridDim.x * blockDim.x) {
        float x; __nv_bfloat16 *hp, *lp;
        if (idx < NS) {
            x = src[idx];
            hp = &g_srcs[0][idx]; lp = &g_srcs[1][idx];
        } else if (idx < N0) {
            long j = idx - NS; int n = (int)(j / 576), k = (int)(j % 576);
            x = (k < 64) ? eW0i[n * 64 + k] : eW0h[n * 512 + k - 64];
            hp = &g_eW0[0][j]; lp = &g_eW0[1][j];
        } else if (idx < N1) {
            long j = idx - N0; int n = (int)(j / 1024), k = (int)(j % 1024);
            x = (k < 512) ? eW1i[n * 512 + k] : eW1h[n * 512 + k - 512];
            hp = &g_eW1[0][j]; lp = &g_eW1[1][j];
        } else if (idx < N2) {
            long j = idx - N1;
            x = dW0h[j];
            hp = &g_dW0[0][j]; lp = &g_dW0[1][j];
        } else if (idx < N3) {
            long j = idx - N2; int n = (int)(j / 1024), k = (int)(j % 1024);
            x = (k < 512) ? dW1i[n * 512 + k] : dW1h[n * 512 + k - 512];
            hp = &g_dW1[0][j]; lp = &g_dW1[1][j];
        } else {
            long j = idx - N3;
            x = fW0[j];
            hp = &g_fW0[0][j]; lp = &g_fW0[1][j];
        }
        __nv_bfloat16 hi = __float2bfloat16_rn(x);
        *hp = hi;
        *lp = __float2bfloat16_rn(x - __bfloat162float(hi));
    }
}

extern "C" __global__ void __launch_bounds__(NTHREADS, 1)
lstm_seq2seq(const float* __restrict__ tgt,
             const float* __restrict__ eB0i, const float* __restrict__ eB0h,
             const float* __restrict__ dW0i,
             const float* __restrict__ dB0i, const float* __restrict__ dB0h,
             const float* __restrict__ eB1i, const float* __restrict__ eB1h,
             const float* __restrict__ dB1i, const float* __restrict__ dB1h,
             const float* __restrict__ fb0,
             const float* __restrict__ fW1, const float* __restrict__ fb1,
             float* __restrict__ out)
{
    extern __shared__ char smem_raw[];
    SMt& sm = *reinterpret_cast<SMt*>(smem_raw);
    const int tid = threadIdx.x;
    const int blk = blockIdx.x;
    const int jt = blk & 31;   // 32 j-tiles of 16 h-columns
    const int mt = blk >> 5;   // 4 batch tiles of 64
    const int b0 = mt * 64;
    const int bg = tid >> 4, jj = tid & 15;
    const int j = jt * 16 + jj;
    const int jbase = jt * 16;

    float biasE0[4], biasE1[4], biasD0[4], biasD1[4], dwi[4];
    #pragma unroll
    for (int gate = 0; gate < 4; ++gate) {
        int g = gate * Hh + j;
        biasE0[gate] = eB0i[g] + eB0h[g];
        biasE1[gate] = eB1i[g] + eB1h[g];
        biasD0[gate] = dB0i[g] + dB0h[g];
        biasD1[gate] = dB1i[g] + dB1h[g];
        dwi[gate]    = dW0i[g];
    }

    // ---- init: zero h planes, load decoder x0 ----
    const __nv_bfloat16 z = __float2bfloat16(0.f);
    #pragma unroll
    for (int bi = 0; bi < 4; ++bi) {
        int idx = (b0 + bg * 4 + bi) * Hh + j;
        hH0[0][0][idx] = z; hH0[0][1][idx] = z; hH0[1][0][idx] = z; hH0[1][1][idx] = z;
        hH1[0][0][idx] = z; hH1[0][1][idx] = z; hH1[1][0][idx] = z; hH1[1][1][idx] = z;
    }
    if (jt == 0 && tid < 64) d_XD[b0 + tid] = tgt[(b0 + tid) * TGTT];

    float cA[4] = {0.f, 0.f, 0.f, 0.f};
    float cB[4] = {0.f, 0.f, 0.f, 0.f};
    float acc[2][2][4];
    grid_sync();

    // ================= encoder (wavefront: L0 step t || L1 step t-1) =================
    int p0 = 0, p1 = 0;
    for (int st = 0; st <= SRCT; ++st) {
        if (st < SRCT) {                       // layer 0 at t = st
            const int t = st;
            auto gah = [&](int s, int r) -> const __nv_bfloat16* {
                int b = b0 + r;
                return (s == 0) ? (g_srcs[0] + ((size_t)b * SRCT + t) * INMM)
                                : (hH0[p0][0] + b * Hh + (s - 1) * 64);
            };
            auto gal = [&](int s, int r) -> const __nv_bfloat16* {
                int b = b0 + r;
                return (s == 0) ? (g_srcs[1] + ((size_t)b * SRCT + t) * INMM)
                                : (hH0[p0][1] + b * Hh + (s - 1) * 64);
            };
            auto gwh = [&](int s, int r) -> const __nv_bfloat16* {
                int g = (r >> 4) * Hh + jbase + (r & 15);
                return g_eW0[0] + (size_t)g * 576 + s * 64;
            };
            auto gwl = [&](int s, int r) -> const __nv_bfloat16* {
                int g = (r >> 4) * Hh + jbase + (r & 15);
                return g_eW0[1] + (size_t)g * 576 + s * 64;
            };
            tgemm(sm, 9, gah, gal, gwh, gwl, acc);
            bool last = (t == SRCT - 1);
            cell_epi(sm, cA, biasE0, b0, bg, jj, j,
                     hH0[p0 ^ 1][0], hH0[p0 ^ 1][1],
                     last ? hHd0[0][0] : (__nv_bfloat16*)nullptr, last ? hHd0[0][1] : (__nv_bfloat16*)nullptr,
                     nullptr, nullptr, nullptr, nullptr);
        }
        if (st >= 1) {                         // layer 1 at t = st-1
            const int t = st - 1;
            auto gah = [&](int s, int r) -> const __nv_bfloat16* {
                int b = b0 + r;
                return (s < 8) ? (hH0[p0][0] + b * Hh + s * 64)
                               : (hH1[p1][0] + b * Hh + (s - 8) * 64);
            };
            auto gal = [&](int s, int r) -> const __nv_bfloat16* {
                int b = b0 + r;
                return (s < 8) ? (hH0[p0][1] + b * Hh + s * 64)
                               : (hH1[p1][1] + b * Hh + (s - 8) * 64);
            };
            auto gwh = [&](int s, int r) -> const __nv_bfloat16* {
                int g = (r >> 4) * Hh + jbase + (r & 15);
                return g_eW1[0] + (size_t)g * 1024 + s * 64;
            };
            auto gwl = [&](int s, int r) -> const __nv_bfloat16* {
                int g = (r >> 4) * Hh + jbase + (r & 15);
                return g_eW1[1] + (size_t)g * 1024 + s * 64;
            };
            tgemm(sm, 16, gah, gal, gwh, gwl, acc);
            bool last = (t == SRCT - 1);
            cell_epi(sm, cB, biasE1, b0, bg, jj, j,
                     hH1[p1 ^ 1][0], hH1[p1 ^ 1][1],
                     last ? hHd1[0][0] : (__nv_bfloat16*)nullptr, last ? hHd1[0][1] : (__nv_bfloat16*)nullptr,
                     nullptr, nullptr, nullptr, nullptr);
        }
        grid_sync();
        p0 ^= 1; p1 ^= 1;
    }

    // ================= autoregressive decoder =================
    int pd0 = 0, pd1 = 0;
    for (int t = 0; t < TGTT; ++t) {
        // ---- stage A: decoder layer 0 (h GEMM + rank-1 x term in epilogue) ----
        {
            auto gah = [&](int s, int r) -> const __nv_bfloat16* {
                return hHd0[pd0][0] + (b0 + r) * Hh + s * 64;
            };
            auto gal = [&](int s, int r) -> const __nv_bfloat16* {
                return hHd0[pd0][1] + (b0 + r) * Hh + s * 64;
            };
            auto gwh = [&](int s, int r) -> const __nv_bfloat16* {
                int g = (r >> 4) * Hh + jbase + (r & 15);
                return g_dW0[0] + (size_t)g * 512 + s * 64;
            };
            auto gwl = [&](int s, int r) -> const __nv_bfloat16* {
                int g = (r >> 4) * Hh + jbase + (r & 15);
                return g_dW0[1] + (size_t)g * 512 + s * 64;
            };
            tgemm(sm, 8, gah, gal, gwh, gwl, acc);
            float xv[4];
            #pragma unroll
            for (int bi = 0; bi < 4; ++bi) xv[bi] = __ldcg(&d_XD[b0 + bg * 4 + bi]);
            cell_epi(sm, cA, biasD0, b0, bg, jj, j,
                     hHd0[pd0 ^ 1][0], hHd0[pd0 ^ 1][1],
                     nullptr, nullptr, nullptr, nullptr, xv, dwi);
        }
        grid_sync(); pd0 ^= 1;

        // ---- stage B: decoder layer 1 (writes h planes + relu planes for fc) ----
        {
            auto gah = [&](int s, int r) -> const __nv_bfloat16* {
                int b = b0 + r;
                return (s < 8) ? (hHd0[pd0][0] + b * Hh + s * 64)
                               : (hHd1[pd1][0] + b * Hh + (s - 8) * 64);
            };
            auto gal = [&](int s, int r) -> const __nv_bfloat16* {
                int b = b0 + r;
                return (s < 8) ? (hHd0[pd0][1] + b * Hh + s * 64)
                               : (hHd1[pd1][1] + b * Hh + (s - 8) * 64);
            };
            auto gwh = [&](int s, int r) -> const __nv_bfloat16* {
                int g = (r >> 4) * Hh + jbase + (r & 15);
                return g_dW1[0] + (size_t)g * 1024 + s * 64;
            };
            auto gwl = [&](int s, int r) -> const __nv_bfloat16* {
                int g = (r >> 4) * Hh + jbase + (r & 15);
                return g_dW1[1] + (size_t)g * 1024 + s * 64;
            };
            tgemm(sm, 16, gah, gal, gwh, gwl, acc);
            cell_epi(sm, cB, biasD1, b0, bg, jj, j,
                     hHd1[pd1 ^ 1][0], hHd1[pd1 ^ 1][1],
                     nullptr, nullptr, d_FCr[0], d_FCr[1], nullptr, nullptr);
        }
        grid_sync(); pd1 ^= 1;

        // ---- stage C: fc hidden = relu(FCr @ W0^T + b0), blocks jt<8 ----
        if (jt < 8) {
            auto gah = [&](int s, int r) -> const __nv_bfloat16* {
                return d_FCr[0] + (b0 + r) * Hh + s * 64;
            };
            auto gal = [&](int s, int r) -> const __nv_bfloat16* {
                return d_FCr[1] + (b0 + r) * Hh + s * 64;
            };
            auto gwh = [&](int s, int r) -> const __nv_bfloat16* {
                return g_fW0[0] + (size_t)(jt * 64 + r) * 512 + s * 64;
            };
            auto gwl = [&](int s, int r) -> const __nv_bfloat16* {
                return g_fW0[1] + (size_t)(jt * 64 + r) * 512 + s * 64;
            };
            tgemm(sm, 8, gah, gal, gwh, gwl, acc);
            #pragma unroll
            for (int q = 0; q < 4; ++q) {
                int gc = jt * 64 + q * 16 + jj;
                float bb = __ldg(&fb0[gc]);
                #pragma unroll
                for (int bi = 0; bi < 4; ++bi) {
                    float v = sm.epi[bg * 4 + bi][q * 16 + jj] + bb;
                    d_FCA[(b0 + bg * 4 + bi) * Hh + gc] = v > 0.f ? v : 0.f;
                }
            }
        }
        grid_sync();

        // ---- stage D: out = a @ W1^T + b1 (scalar), feed back as next x ----
        if (jt == 0) {
            int bb = tid >> 2, q = tid & 3;
            int b = b0 + bb;
            float sum = 0.f;
            for (int k = q * 128; k < q * 128 + 128; k += 4) {
                float4 av = __ldcg((const float4*)&d_FCA[b * Hh + k]);
                float4 wv = *(const float4*)&fW1[k];
                sum += av.x * wv.x + av.y * wv.y + av.z * wv.z + av.w * wv.w;
            }
            sum += __shfl_xor_sync(0xffffffffu, sum, 1);
            sum += __shfl_xor_sync(0xffffffffu, sum, 2);
            if (q == 0) {
                float o = sum + __ldg(&fb1[0]);
                out[b * TGTT + t] = o;
                d_XD[b] = o;
            }
        }
        grid_sync();
    }
}

extern "C" void kernel_launch(void* const* d_in, const int* in_sizes, int n_in,
                              void* d_out, int out_size)
{
    const float* src  = (const float*)d_in[0];
    const float* tgt  = (const float*)d_in[1];
    const float* eW0i = (const float*)d_in[2];
    const float* eW0h = (const float*)d_in[3];
    const float* eB0i = (const float*)d_in[4];
    const float* eB0h = (const float*)d_in[5];
    const float* dW0i = (const float*)d_in[6];
    const float* dW0h = (const float*)d_in[7];
    const float* dB0i = (const float*)d_in[8];
    const float* dB0h = (const float*)d_in[9];
    const float* eW1i = (const float*)d_in[10];
    const float* eW1h = (const float*)d_in[11];
    const float* eB1i = (const float*)d_in[12];
    const float* eB1h = (const float*)d_in[13];
    const float* dW1i = (const float*)d_in[14];
    const float* dW1h = (const float*)d_in[15];
    const float* dB1i = (const float*)d_in[16];
    const float* dB1h = (const float*)d_in[17];
    const float* fW0  = (const float*)d_in[18];
    const float* fb0  = (const float*)d_in[19];
    const float* fW1  = (const float*)d_in[20];
    const float* fb1  = (const float*)d_in[21];

    static int smem_set = 0;
    if (!smem_set) {
        cudaFuncSetAttribute(lstm_seq2seq, cudaFuncAttributeMaxDynamicSharedMemorySize,
                             (int)sizeof(SMt));
        smem_set = 1;
    }

    prep_weights<<<1024, 256>>>(src, eW0i, eW0h, eW1i, eW1h, dW0h, dW1i, dW1h, fW0);

    lstm_seq2seq<<<GRID_BLOCKS, NTHREADS, sizeof(SMt)>>>(
        tgt,
        eB0i, eB0h,
        dW0i, dB0i, dB0h,
        eB1i, eB1h,
        dB1i, dB1h,
        fb0, fW1, fb1,
        (float*)d_out);
}